// round 2
// baseline (speedup 1.0000x reference)
#include <cuda_runtime.h>
#include <cstdint>

// Problem constants
#define Bc 4
#define Sc 1024
#define Hc 1024
#define NHc 16
#define HDc 64
#define BHc (Bc * NHc)                 // 64
#define Mrows (Bc * Sc)                // 4096
#define CTX_ELEMS (Bc * Sc * Hc)       // 4194304
#define SCORES_ELEMS (BHc * Sc * Sc)   // 67108864

// Scratch (device globals — no runtime allocation allowed)
__device__ float g_q[BHc * Sc * HDc];   // [bh][s][d]
__device__ float g_k[BHc * Sc * HDc];
__device__ float g_v[BHc * Sc * HDc];
__device__ float g_m[BHc * Sc];         // row max
__device__ float g_invz[BHc * Sc];      // 1 / sum exp
__device__ float g_scores_scratch[SCORES_ELEMS]; // fallback if scores not in d_out

// ---------------------------------------------------------------------------
// Kernel 1: QKV projection.  y[m,n] = sum_k X[m,k]*W[n,k] + b[n]
// NT GEMM, M=4096 N=1024 K=1024, tiles 128x128x16, 256 threads, 8x8/thread.
// Output in head-major layout g_{q,k,v}[bh][s][d].
// ---------------------------------------------------------------------------
__global__ __launch_bounds__(256, 2)
void qkv_kernel(const float* __restrict__ qin, const float* __restrict__ kin,
                const float* __restrict__ vin,
                const float* __restrict__ Wq, const float* __restrict__ bq,
                const float* __restrict__ Wk, const float* __restrict__ bk,
                const float* __restrict__ Wv, const float* __restrict__ bv)
{
    const int which = blockIdx.z;
    const float* X    = (which == 0) ? qin : (which == 1) ? kin : vin;
    const float* W    = (which == 0) ? Wq  : (which == 1) ? Wk  : Wv;
    const float* bias = (which == 0) ? bq  : (which == 1) ? bk  : bv;
    float* out        = (which == 0) ? g_q : (which == 1) ? g_k : g_v;

    const int BM = 128, BN = 128, BK = 16;
    __shared__ float As[BK][BM + 4];   // transposed: As[k][m]
    __shared__ float Bs[BK][BN + 4];

    const int m0 = blockIdx.y * BM;
    const int n0 = blockIdx.x * BN;
    const int tid = threadIdx.x;
    const int tx = tid & 15, ty = tid >> 4;

    float acc[8][8];
#pragma unroll
    for (int i = 0; i < 8; i++)
#pragma unroll
        for (int j = 0; j < 8; j++) acc[i][j] = 0.f;

    for (int k0 = 0; k0 < Hc; k0 += BK) {
#pragma unroll
        for (int l = 0; l < 2; l++) {
            int v  = tid + l * 256;      // 0..511 -> 128 rows x 4 float4
            int r  = v >> 2;
            int kq = v & 3;
            float4 a = *(const float4*)&X[(size_t)(m0 + r) * Hc + k0 + kq * 4];
            As[kq * 4 + 0][r] = a.x; As[kq * 4 + 1][r] = a.y;
            As[kq * 4 + 2][r] = a.z; As[kq * 4 + 3][r] = a.w;
            float4 b = *(const float4*)&W[(size_t)(n0 + r) * Hc + k0 + kq * 4];
            Bs[kq * 4 + 0][r] = b.x; Bs[kq * 4 + 1][r] = b.y;
            Bs[kq * 4 + 2][r] = b.z; Bs[kq * 4 + 3][r] = b.w;
        }
        __syncthreads();
#pragma unroll
        for (int k = 0; k < BK; k++) {
            float a[8], b[8];
            *(float4*)&a[0] = *(const float4*)&As[k][ty * 8];
            *(float4*)&a[4] = *(const float4*)&As[k][ty * 8 + 4];
            *(float4*)&b[0] = *(const float4*)&Bs[k][tx * 8];
            *(float4*)&b[4] = *(const float4*)&Bs[k][tx * 8 + 4];
#pragma unroll
            for (int i = 0; i < 8; i++)
#pragma unroll
                for (int j = 0; j < 8; j++) acc[i][j] += a[i] * b[j];
        }
        __syncthreads();
    }

    // Epilogue: add bias, write head-major out[bh][s][d]
#pragma unroll
    for (int i = 0; i < 8; i++) {
        int m = m0 + ty * 8 + i;
        int b = m >> 10;           // batch
        int s = m & 1023;
#pragma unroll
        for (int jj = 0; jj < 8; jj += 4) {
            int n = n0 + tx * 8 + jj;
            int h = n >> 6;
            int d = n & 63;
            float4 bv4 = *(const float4*)&bias[n];
            float4 r;
            r.x = acc[i][jj + 0] + bv4.x;
            r.y = acc[i][jj + 1] + bv4.y;
            r.z = acc[i][jj + 2] + bv4.z;
            r.w = acc[i][jj + 3] + bv4.w;
            *(float4*)&out[(((size_t)(b * NHc + h)) << 16) + ((size_t)s << 6) + d] = r;
        }
    }
}

// ---------------------------------------------------------------------------
// Kernel 2: scores[bh][i][j] = (Q[bh][i]·K[bh][j]) / 8 + (mask ? -9999 : 0)
// Mask is int32 (bool widened by harness). Per-bh 64x64 tiles, K=64 resident.
// ---------------------------------------------------------------------------
__global__ __launch_bounds__(256, 2)
void scores_kernel(const int* __restrict__ mask,
                   float* __restrict__ scores)
{
    const int bh = blockIdx.z;
    const int i0 = blockIdx.y * 64;
    const int j0 = blockIdx.x * 64;
    const float* Q = g_q + (size_t)bh * Sc * HDc;
    const float* K = g_k + (size_t)bh * Sc * HDc;

    __shared__ float Qs[64][68];   // [d][i]
    __shared__ float Ks[64][68];   // [d][j]

    const int tid = threadIdx.x;
    const int tx = tid & 15, ty = tid >> 4;

#pragma unroll
    for (int l = 0; l < 4; l++) {
        int v  = tid + l * 256;    // 0..1023 -> 64 rows x 16 float4
        int r  = v >> 4;
        int dq = v & 15;
        float4 q = *(const float4*)&Q[(size_t)(i0 + r) * HDc + dq * 4];
        Qs[dq * 4 + 0][r] = q.x; Qs[dq * 4 + 1][r] = q.y;
        Qs[dq * 4 + 2][r] = q.z; Qs[dq * 4 + 3][r] = q.w;
        float4 k = *(const float4*)&K[(size_t)(j0 + r) * HDc + dq * 4];
        Ks[dq * 4 + 0][r] = k.x; Ks[dq * 4 + 1][r] = k.y;
        Ks[dq * 4 + 2][r] = k.z; Ks[dq * 4 + 3][r] = k.w;
    }
    __syncthreads();

    float acc[4][4];
#pragma unroll
    for (int i = 0; i < 4; i++)
#pragma unroll
        for (int j = 0; j < 4; j++) acc[i][j] = 0.f;

#pragma unroll
    for (int k = 0; k < 64; k++) {
        float4 a = *(const float4*)&Qs[k][ty * 4];
        float4 b = *(const float4*)&Ks[k][tx * 4];
        acc[0][0] += a.x * b.x; acc[0][1] += a.x * b.y; acc[0][2] += a.x * b.z; acc[0][3] += a.x * b.w;
        acc[1][0] += a.y * b.x; acc[1][1] += a.y * b.y; acc[1][2] += a.y * b.z; acc[1][3] += a.y * b.w;
        acc[2][0] += a.z * b.x; acc[2][1] += a.z * b.y; acc[2][2] += a.z * b.z; acc[2][3] += a.z * b.w;
        acc[3][0] += a.w * b.x; acc[3][1] += a.w * b.y; acc[3][2] += a.w * b.z; acc[3][3] += a.w * b.w;
    }

#pragma unroll
    for (int i = 0; i < 4; i++) {
        int row = i0 + ty * 4 + i;
        size_t base = ((size_t)bh * Sc + row) * Sc + j0 + tx * 4;
        int4 mk = *(const int4*)&mask[base];   // int32 mask, 4 elems = 16B
        float4 r;
        r.x = acc[i][0] * 0.125f + (mk.x ? -9999.0f : 0.0f);
        r.y = acc[i][1] * 0.125f + (mk.y ? -9999.0f : 0.0f);
        r.z = acc[i][2] * 0.125f + (mk.z ? -9999.0f : 0.0f);
        r.w = acc[i][3] * 0.125f + (mk.w ? -9999.0f : 0.0f);
        *(float4*)&scores[base] = r;
    }
}

// ---------------------------------------------------------------------------
// Kernel 3: per-row softmax stats. One warp per 1024-element row, single pass.
// ---------------------------------------------------------------------------
__global__ __launch_bounds__(256)
void stats_kernel(const float* __restrict__ scores)
{
    const int warp = threadIdx.x >> 5;
    const int lane = threadIdx.x & 31;
    const int r = blockIdx.x * 8 + warp;    // 0 .. 65535
    const float* row = scores + (size_t)r * Sc;

    float vals[32];
    float vmax = -3.4e38f;
#pragma unroll
    for (int k = 0; k < 8; k++) {
        float4 f = *(const float4*)&row[k * 128 + lane * 4];
        vals[k * 4 + 0] = f.x; vals[k * 4 + 1] = f.y;
        vals[k * 4 + 2] = f.z; vals[k * 4 + 3] = f.w;
        vmax = fmaxf(vmax, fmaxf(fmaxf(f.x, f.y), fmaxf(f.z, f.w)));
    }
#pragma unroll
    for (int o = 16; o > 0; o >>= 1)
        vmax = fmaxf(vmax, __shfl_xor_sync(0xffffffffu, vmax, o));

    float sum = 0.f;
#pragma unroll
    for (int k = 0; k < 32; k++) sum += __expf(vals[k] - vmax);
#pragma unroll
    for (int o = 16; o > 0; o >>= 1)
        sum += __shfl_xor_sync(0xffffffffu, sum, o);

    if (lane == 0) {
        g_m[r] = vmax;
        g_invz[r] = 1.0f / sum;
    }
}

// ---------------------------------------------------------------------------
// Kernel 4: ctx = softmax(scores) @ V, written as [B,S,H].
// ---------------------------------------------------------------------------
__global__ __launch_bounds__(256, 2)
void pv_kernel(const float* __restrict__ scores, float* __restrict__ ctx)
{
    const int bh = blockIdx.y;
    const int i0 = blockIdx.x * 64;
    const float* V = g_v + (size_t)bh * Sc * HDc;

    __shared__ float Ps[64][68];   // [j][i]
    __shared__ float Vs[64][68];   // [j][d]
    __shared__ float ms[64];
    __shared__ float zs[64];

    const int tid = threadIdx.x;
    const int tx = tid & 15, ty = tid >> 4;

    if (tid < 64) {
        ms[tid] = g_m[(size_t)bh * Sc + i0 + tid];
        zs[tid] = g_invz[(size_t)bh * Sc + i0 + tid];
    }
    __syncthreads();

    float acc[4][4];
#pragma unroll
    for (int i = 0; i < 4; i++)
#pragma unroll
        for (int j = 0; j < 4; j++) acc[i][j] = 0.f;

    for (int jt = 0; jt < 16; jt++) {
        int j0 = jt * 64;
#pragma unroll
        for (int l = 0; l < 4; l++) {
            int v  = tid + l * 256;
            int r  = v >> 4;       // 0..63
            int cq = v & 15;
            // scores tile, exp'd, transposed into Ps[j][i]
            float4 s = *(const float4*)&scores[((size_t)bh * Sc + i0 + r) * Sc + j0 + cq * 4];
            float mi = ms[r];
            Ps[cq * 4 + 0][r] = __expf(s.x - mi);
            Ps[cq * 4 + 1][r] = __expf(s.y - mi);
            Ps[cq * 4 + 2][r] = __expf(s.z - mi);
            Ps[cq * 4 + 3][r] = __expf(s.w - mi);
            // V tile direct
            float4 vv = *(const float4*)&V[(size_t)(j0 + r) * HDc + (cq & 15) * 4];
            *(float4*)&Vs[r][(cq & 15) * 4] = vv;
        }
        __syncthreads();
#pragma unroll
        for (int j = 0; j < 64; j++) {
            float4 p = *(const float4*)&Ps[j][ty * 4];
            float4 v = *(const float4*)&Vs[j][tx * 4];
            acc[0][0] += p.x * v.x; acc[0][1] += p.x * v.y; acc[0][2] += p.x * v.z; acc[0][3] += p.x * v.w;
            acc[1][0] += p.y * v.x; acc[1][1] += p.y * v.y; acc[1][2] += p.y * v.z; acc[1][3] += p.y * v.w;
            acc[2][0] += p.z * v.x; acc[2][1] += p.z * v.y; acc[2][2] += p.z * v.z; acc[2][3] += p.z * v.w;
            acc[3][0] += p.w * v.x; acc[3][1] += p.w * v.y; acc[3][2] += p.w * v.z; acc[3][3] += p.w * v.w;
        }
        __syncthreads();
    }

    // ctx[b][s][h*64+d]
    const int b = bh >> 4;
    const int h = bh & 15;
#pragma unroll
    for (int i = 0; i < 4; i++) {
        int row = i0 + ty * 4 + i;
        float inz = zs[ty * 4 + i];
        float4 r;
        r.x = acc[i][0] * inz; r.y = acc[i][1] * inz;
        r.z = acc[i][2] * inz; r.w = acc[i][3] * inz;
        *(float4*)&ctx[((size_t)b * Sc + row) * Hc + h * HDc + tx * 4] = r;
    }
}

// ---------------------------------------------------------------------------
extern "C" void kernel_launch(void* const* d_in, const int* in_sizes, int n_in,
                              void* d_out, int out_size)
{
    const float* qin = (const float*)d_in[0];
    const float* kin = (const float*)d_in[1];
    const float* vin = (const float*)d_in[2];
    const int* mask  = (const int*)d_in[3];      // bool widened to int32
    const float* Wq = (const float*)d_in[4];
    const float* bq = (const float*)d_in[5];
    const float* Wk = (const float*)d_in[6];
    const float* bk = (const float*)d_in[7];
    const float* Wv = (const float*)d_in[8];
    const float* bv = (const float*)d_in[9];

    float* ctx = (float*)d_out;
    float* scores;
    if (out_size >= CTX_ELEMS + SCORES_ELEMS) {
        scores = (float*)d_out + CTX_ELEMS;          // tuple output (ctx, scores)
    } else {
        // fallback: scores not part of output — use scratch
        cudaGetSymbolAddress((void**)&scores, g_scores_scratch);
    }

    // 1) QKV projections
    {
        dim3 grid(Hc / 128, Mrows / 128, 3);
        qkv_kernel<<<grid, 256>>>(qin, kin, vin, Wq, bq, Wk, bk, Wv, bv);
    }
    // 2) scores = QK^T/8 + mask
    {
        dim3 grid(Sc / 64, Sc / 64, BHc);
        scores_kernel<<<grid, 256>>>(mask, scores);
    }
    // 3) softmax stats
    {
        stats_kernel<<<(BHc * Sc) / 8, 256>>>(scores);
    }
    // 4) ctx = softmax(scores) @ V
    {
        dim3 grid(Sc / 64, BHc);
        pv_kernel<<<grid, 256>>>(scores, ctx);
    }
}

// round 10
// speedup vs baseline: 1.4921x; 1.4921x over previous
#include <cuda_runtime.h>
#include <cstdint>

// Problem constants
#define Bc 4
#define Sc 1024
#define Hc 1024
#define NHc 16
#define HDc 64
#define BHc (Bc * NHc)                 // 64
#define Mrows (Bc * Sc)                // 4096
#define CTX_ELEMS (Bc * Sc * Hc)       // 4194304
#define SCORES_ELEMS (BHc * Sc * Sc)   // 67108864

// Scratch (device globals — no runtime allocation allowed)
__device__ float g_q[BHc * Sc * HDc];   // [bh][s][d]
__device__ float g_k[BHc * Sc * HDc];
__device__ float g_v[BHc * Sc * HDc];
__device__ float g_m[BHc * Sc];         // row max
__device__ float g_invz[BHc * Sc];      // 1 / sum exp
__device__ float g_scores_scratch[SCORES_ELEMS]; // fallback if scores not in d_out

// ---------------------------------------------------------------------------
// tf32 helpers (legacy tensor-core path: works on compute_103 baseline)
// ---------------------------------------------------------------------------
__device__ __forceinline__ uint32_t f2tf32(float f) {
    uint32_t r;
    asm("cvt.rna.tf32.f32 %0, %1;" : "=r"(r) : "f"(f));
    return r;
}

__device__ __forceinline__ void mma_tf32(float (&d)[4],
                                         const uint32_t (&a)[4],
                                         const uint32_t (&b)[2],
                                         const float (&c)[4]) {
    asm volatile(
        "mma.sync.aligned.m16n8k8.row.col.f32.tf32.tf32.f32 "
        "{%0,%1,%2,%3}, {%4,%5,%6,%7}, {%8,%9}, {%10,%11,%12,%13};"
        : "=f"(d[0]), "=f"(d[1]), "=f"(d[2]), "=f"(d[3])
        : "r"(a[0]), "r"(a[1]), "r"(a[2]), "r"(a[3]),
          "r"(b[0]), "r"(b[1]),
          "f"(c[0]), "f"(c[1]), "f"(c[2]), "f"(c[3]));
}

// ---------------------------------------------------------------------------
// Kernel 1: QKV projection via mma.sync tf32.
// y[m,n] = sum_k X[m,k]*W[n,k] + b[n]   (NT GEMM -> row.col fragments)
// Tile 128x128xBK=32, 256 thr = 8 warps (2x4), warp tile 64x32 (4x4 frags).
// Output head-major g_{q,k,v}[bh][s][d].
// ---------------------------------------------------------------------------
#define KSTRIDE 36   // 32 + 4 pad: rotates banks by 4 per row -> conflict-free frags

__global__ __launch_bounds__(256, 2)
void qkv_mma_kernel(const float* __restrict__ qin, const float* __restrict__ kin,
                    const float* __restrict__ vin,
                    const float* __restrict__ Wq, const float* __restrict__ bq,
                    const float* __restrict__ Wk, const float* __restrict__ bk,
                    const float* __restrict__ Wv, const float* __restrict__ bv)
{
    const int which = blockIdx.z;
    const float* X    = (which == 0) ? qin : (which == 1) ? kin : vin;
    const float* W    = (which == 0) ? Wq  : (which == 1) ? Wk  : Wv;
    const float* bias = (which == 0) ? bq  : (which == 1) ? bk  : bv;
    float* out        = (which == 0) ? g_q : (which == 1) ? g_k : g_v;

    __shared__ uint32_t As[128][KSTRIDE];   // X tile  [m][k], tf32 bits
    __shared__ uint32_t Bs[128][KSTRIDE];   // W tile  [n][k], tf32 bits

    const int m0 = blockIdx.y * 128;
    const int n0 = blockIdx.x * 128;
    const int tid = threadIdx.x;
    const int warp = tid >> 5, lane = tid & 31;
    const int wm = warp >> 2;          // 0..1  -> 64-row slab
    const int wn = warp & 3;           // 0..3  -> 32-col slab
    const int qr = lane >> 2;          // 0..7
    const int qc = lane & 3;           // 0..3

    float acc[4][4][4];
#pragma unroll
    for (int mi = 0; mi < 4; mi++)
#pragma unroll
        for (int ni = 0; ni < 4; ni++)
#pragma unroll
            for (int e = 0; e < 4; e++) acc[mi][ni][e] = 0.f;

    for (int k0 = 0; k0 < Hc; k0 += 32) {
        // Stage tiles: 128 rows x 8 float4 each for A and B
#pragma unroll
        for (int l = 0; l < 4; l++) {
            int idx = tid + l * 256;       // 0..1023
            int r = idx >> 3;              // 0..127
            int q = idx & 7;               // float4 index
            float4 a = *(const float4*)&X[(size_t)(m0 + r) * Hc + k0 + q * 4];
            As[r][q * 4 + 0] = f2tf32(a.x); As[r][q * 4 + 1] = f2tf32(a.y);
            As[r][q * 4 + 2] = f2tf32(a.z); As[r][q * 4 + 3] = f2tf32(a.w);
            float4 w = *(const float4*)&W[(size_t)(n0 + r) * Hc + k0 + q * 4];
            Bs[r][q * 4 + 0] = f2tf32(w.x); Bs[r][q * 4 + 1] = f2tf32(w.y);
            Bs[r][q * 4 + 2] = f2tf32(w.z); Bs[r][q * 4 + 3] = f2tf32(w.w);
        }
        __syncthreads();

#pragma unroll
        for (int ks = 0; ks < 4; ks++) {
            const int kk = ks * 8;
            uint32_t af[4][4];
#pragma unroll
            for (int mi = 0; mi < 4; mi++) {
                int row = wm * 64 + mi * 16 + qr;
                af[mi][0] = As[row    ][kk + qc];
                af[mi][1] = As[row + 8][kk + qc];
                af[mi][2] = As[row    ][kk + qc + 4];
                af[mi][3] = As[row + 8][kk + qc + 4];
            }
            uint32_t bf[4][2];
#pragma unroll
            for (int ni = 0; ni < 4; ni++) {
                int col = wn * 32 + ni * 8 + qr;
                bf[ni][0] = Bs[col][kk + qc];
                bf[ni][1] = Bs[col][kk + qc + 4];
            }
#pragma unroll
            for (int mi = 0; mi < 4; mi++)
#pragma unroll
                for (int ni = 0; ni < 4; ni++)
                    mma_tf32(acc[mi][ni], af[mi], bf[ni], acc[mi][ni]);
        }
        __syncthreads();
    }

    // Epilogue. c frag: c0=(qr, 2qc) c1=(qr, 2qc+1) c2=(qr+8, 2qc) c3=(qr+8, 2qc+1)
#pragma unroll
    for (int mi = 0; mi < 4; mi++) {
#pragma unroll
        for (int half = 0; half < 2; half++) {
            int m = m0 + wm * 64 + mi * 16 + qr + half * 8;
            int bb = m >> 10;
            int s  = m & 1023;
#pragma unroll
            for (int ni = 0; ni < 4; ni++) {
                int n = n0 + wn * 32 + ni * 8 + qc * 2;
                int h = n >> 6, d = n & 63;
                float2 r;
                r.x = acc[mi][ni][half * 2 + 0] + bias[n];
                r.y = acc[mi][ni][half * 2 + 1] + bias[n + 1];
                *(float2*)&out[(((size_t)(bb * NHc + h)) << 16) + ((size_t)s << 6) + d] = r;
            }
        }
    }
}

// ---------------------------------------------------------------------------
// Kernel 2: scores[bh][i][j] = (Q[bh][i]·K[bh][j]) / 8 + (mask ? -9999 : 0)
// ---------------------------------------------------------------------------
__global__ __launch_bounds__(256, 2)
void scores_kernel(const int* __restrict__ mask,
                   float* __restrict__ scores)
{
    const int bh = blockIdx.z;
    const int i0 = blockIdx.y * 64;
    const int j0 = blockIdx.x * 64;
    const float* Q = g_q + (size_t)bh * Sc * HDc;
    const float* K = g_k + (size_t)bh * Sc * HDc;

    __shared__ float Qs[64][68];
    __shared__ float Ks[64][68];

    const int tid = threadIdx.x;
    const int tx = tid & 15, ty = tid >> 4;

#pragma unroll
    for (int l = 0; l < 4; l++) {
        int v  = tid + l * 256;
        int r  = v >> 4;
        int dq = v & 15;
        float4 q = *(const float4*)&Q[(size_t)(i0 + r) * HDc + dq * 4];
        Qs[dq * 4 + 0][r] = q.x; Qs[dq * 4 + 1][r] = q.y;
        Qs[dq * 4 + 2][r] = q.z; Qs[dq * 4 + 3][r] = q.w;
        float4 k = *(const float4*)&K[(size_t)(j0 + r) * HDc + dq * 4];
        Ks[dq * 4 + 0][r] = k.x; Ks[dq * 4 + 1][r] = k.y;
        Ks[dq * 4 + 2][r] = k.z; Ks[dq * 4 + 3][r] = k.w;
    }
    __syncthreads();

    float acc[4][4];
#pragma unroll
    for (int i = 0; i < 4; i++)
#pragma unroll
        for (int j = 0; j < 4; j++) acc[i][j] = 0.f;

#pragma unroll
    for (int k = 0; k < 64; k++) {
        float4 a = *(const float4*)&Qs[k][ty * 4];
        float4 b = *(const float4*)&Ks[k][tx * 4];
        acc[0][0] += a.x * b.x; acc[0][1] += a.x * b.y; acc[0][2] += a.x * b.z; acc[0][3] += a.x * b.w;
        acc[1][0] += a.y * b.x; acc[1][1] += a.y * b.y; acc[1][2] += a.y * b.z; acc[1][3] += a.y * b.w;
        acc[2][0] += a.z * b.x; acc[2][1] += a.z * b.y; acc[2][2] += a.z * b.z; acc[2][3] += a.z * b.w;
        acc[3][0] += a.w * b.x; acc[3][1] += a.w * b.y; acc[3][2] += a.w * b.z; acc[3][3] += a.w * b.w;
    }

#pragma unroll
    for (int i = 0; i < 4; i++) {
        int r0 = i0 + ty * 4 + i;
        size_t base = ((size_t)bh * Sc + r0) * Sc + j0 + tx * 4;
        int4 mk = *(const int4*)&mask[base];
        float4 r;
        r.x = acc[i][0] * 0.125f + (mk.x ? -9999.0f : 0.0f);
        r.y = acc[i][1] * 0.125f + (mk.y ? -9999.0f : 0.0f);
        r.z = acc[i][2] * 0.125f + (mk.z ? -9999.0f : 0.0f);
        r.w = acc[i][3] * 0.125f + (mk.w ? -9999.0f : 0.0f);
        *(float4*)&scores[base] = r;
    }
}

// ---------------------------------------------------------------------------
// Kernel 3: per-row softmax stats (one warp per row, single pass).
// ---------------------------------------------------------------------------
__global__ __launch_bounds__(256)
void stats_kernel(const float* __restrict__ scores)
{
    const int warp = threadIdx.x >> 5;
    const int lane = threadIdx.x & 31;
    const int r = blockIdx.x * 8 + warp;
    const float* row = scores + (size_t)r * Sc;

    float vals[32];
    float vmax = -3.4e38f;
#pragma unroll
    for (int k = 0; k < 8; k++) {
        float4 f = *(const float4*)&row[k * 128 + lane * 4];
        vals[k * 4 + 0] = f.x; vals[k * 4 + 1] = f.y;
        vals[k * 4 + 2] = f.z; vals[k * 4 + 3] = f.w;
        vmax = fmaxf(vmax, fmaxf(fmaxf(f.x, f.y), fmaxf(f.z, f.w)));
    }
#pragma unroll
    for (int o = 16; o > 0; o >>= 1)
        vmax = fmaxf(vmax, __shfl_xor_sync(0xffffffffu, vmax, o));

    float sum = 0.f;
#pragma unroll
    for (int k = 0; k < 32; k++) sum += __expf(vals[k] - vmax);
#pragma unroll
    for (int o = 16; o > 0; o >>= 1)
        sum += __shfl_xor_sync(0xffffffffu, sum, o);

    if (lane == 0) {
        g_m[r] = vmax;
        g_invz[r] = 1.0f / sum;
    }
}

// ---------------------------------------------------------------------------
// Kernel 4: ctx = softmax(scores) @ V, written as [B,S,H].
// ---------------------------------------------------------------------------
__global__ __launch_bounds__(256, 2)
void pv_kernel(const float* __restrict__ scores, float* __restrict__ ctx)
{
    const int bh = blockIdx.y;
    const int i0 = blockIdx.x * 64;
    const float* V = g_v + (size_t)bh * Sc * HDc;

    __shared__ float Ps[64][68];
    __shared__ float Vs[64][68];
    __shared__ float ms[64];
    __shared__ float zs[64];

    const int tid = threadIdx.x;
    const int tx = tid & 15, ty = tid >> 4;

    if (tid < 64) {
        ms[tid] = g_m[(size_t)bh * Sc + i0 + tid];
        zs[tid] = g_invz[(size_t)bh * Sc + i0 + tid];
    }
    __syncthreads();

    float acc[4][4];
#pragma unroll
    for (int i = 0; i < 4; i++)
#pragma unroll
        for (int j = 0; j < 4; j++) acc[i][j] = 0.f;

    for (int jt = 0; jt < 16; jt++) {
        int j0 = jt * 64;
#pragma unroll
        for (int l = 0; l < 4; l++) {
            int v  = tid + l * 256;
            int r  = v >> 4;
            int cq = v & 15;
            float4 s = *(const float4*)&scores[((size_t)bh * Sc + i0 + r) * Sc + j0 + cq * 4];
            float mi = ms[r];
            Ps[cq * 4 + 0][r] = __expf(s.x - mi);
            Ps[cq * 4 + 1][r] = __expf(s.y - mi);
            Ps[cq * 4 + 2][r] = __expf(s.z - mi);
            Ps[cq * 4 + 3][r] = __expf(s.w - mi);
            float4 vv = *(const float4*)&V[(size_t)(j0 + r) * HDc + (cq & 15) * 4];
            *(float4*)&Vs[r][(cq & 15) * 4] = vv;
        }
        __syncthreads();
#pragma unroll
        for (int j = 0; j < 64; j++) {
            float4 p = *(const float4*)&Ps[j][ty * 4];
            float4 v = *(const float4*)&Vs[j][tx * 4];
            acc[0][0] += p.x * v.x; acc[0][1] += p.x * v.y; acc[0][2] += p.x * v.z; acc[0][3] += p.x * v.w;
            acc[1][0] += p.y * v.x; acc[1][1] += p.y * v.y; acc[1][2] += p.y * v.z; acc[1][3] += p.y * v.w;
            acc[2][0] += p.z * v.x; acc[2][1] += p.z * v.y; acc[2][2] += p.z * v.z; acc[2][3] += p.z * v.w;
            acc[3][0] += p.w * v.x; acc[3][1] += p.w * v.y; acc[3][2] += p.w * v.z; acc[3][3] += p.w * v.w;
        }
        __syncthreads();
    }

    const int b = bh >> 4;
    const int h = bh & 15;
#pragma unroll
    for (int i = 0; i < 4; i++) {
        int row = i0 + ty * 4 + i;
        float inz = zs[ty * 4 + i];
        float4 r;
        r.x = acc[i][0] * inz; r.y = acc[i][1] * inz;
        r.z = acc[i][2] * inz; r.w = acc[i][3] * inz;
        *(float4*)&ctx[((size_t)b * Sc + row) * Hc + h * HDc + tx * 4] = r;
    }
}

// ---------------------------------------------------------------------------
extern "C" void kernel_launch(void* const* d_in, const int* in_sizes, int n_in,
                              void* d_out, int out_size)
{
    const float* qin = (const float*)d_in[0];
    const float* kin = (const float*)d_in[1];
    const float* vin = (const float*)d_in[2];
    const int* mask  = (const int*)d_in[3];      // bool widened to int32
    const float* Wq = (const float*)d_in[4];
    const float* bq = (const float*)d_in[5];
    const float* Wk = (const float*)d_in[6];
    const float* bk = (const float*)d_in[7];
    const float* Wv = (const float*)d_in[8];
    const float* bv = (const float*)d_in[9];

    float* ctx = (float*)d_out;
    float* scores;
    if (out_size >= CTX_ELEMS + SCORES_ELEMS) {
        scores = (float*)d_out + CTX_ELEMS;          // tuple output (ctx, scores)
    } else {
        cudaGetSymbolAddress((void**)&scores, g_scores_scratch);
    }

    // 1) QKV projections via legacy tensor cores (tf32 mma.sync)
    {
        dim3 grid(Hc / 128, Mrows / 128, 3);
        qkv_mma_kernel<<<grid, 256>>>(qin, kin, vin, Wq, bq, Wk, bk, Wv, bv);
    }
    // 2) scores = QK^T/8 + mask
    {
        dim3 grid(Sc / 64, Sc / 64, BHc);
        scores_kernel<<<grid, 256>>>(mask, scores);
    }
    // 3) softmax stats
    {
        stats_kernel<<<(BHc * Sc) / 8, 256>>>(scores);
    }
    // 4) ctx = softmax(scores) @ V
    {
        dim3 grid(Sc / 64, BHc);
        pv_kernel<<<grid, 256>>>(scores, ctx);
    }
}

// round 11
// speedup vs baseline: 1.8925x; 1.2684x over previous
#include <cuda_runtime.h>
#include <cstdint>

// Problem constants
#define Bc 4
#define Sc 1024
#define Hc 1024
#define NHc 16
#define HDc 64
#define BHc (Bc * NHc)                 // 64
#define Mrows (Bc * Sc)                // 4096
#define CTX_ELEMS (Bc * Sc * Hc)       // 4194304
#define SCORES_ELEMS (BHc * Sc * Sc)   // 67108864

// Scratch (device globals — no runtime allocation allowed)
__device__ float g_q[BHc * Sc * HDc];   // [bh][s][d]
__device__ float g_k[BHc * Sc * HDc];
__device__ float g_v[BHc * Sc * HDc];
__device__ float g_scores_scratch[SCORES_ELEMS]; // fallback if scores not in d_out

// ---------------------------------------------------------------------------
// tf32 helpers (legacy tensor-core path: works on compute_103 baseline)
// ---------------------------------------------------------------------------
__device__ __forceinline__ uint32_t f2tf32(float f) {
    uint32_t r;
    asm("cvt.rna.tf32.f32 %0, %1;" : "=r"(r) : "f"(f));
    return r;
}

__device__ __forceinline__ void mma_tf32(float (&d)[4],
                                         const uint32_t (&a)[4],
                                         const uint32_t (&b)[2],
                                         const float (&c)[4]) {
    asm volatile(
        "mma.sync.aligned.m16n8k8.row.col.f32.tf32.tf32.f32 "
        "{%0,%1,%2,%3}, {%4,%5,%6,%7}, {%8,%9}, {%10,%11,%12,%13};"
        : "=f"(d[0]), "=f"(d[1]), "=f"(d[2]), "=f"(d[3])
        : "r"(a[0]), "r"(a[1]), "r"(a[2]), "r"(a[3]),
          "r"(b[0]), "r"(b[1]),
          "f"(c[0]), "f"(c[1]), "f"(c[2]), "f"(c[3]));
}

// ---------------------------------------------------------------------------
// Kernel 1: QKV projection via mma.sync tf32.  (unchanged from R10 - passing)
// ---------------------------------------------------------------------------
#define KSTRIDE 36

__global__ __launch_bounds__(256, 2)
void qkv_mma_kernel(const float* __restrict__ qin, const float* __restrict__ kin,
                    const float* __restrict__ vin,
                    const float* __restrict__ Wq, const float* __restrict__ bq,
                    const float* __restrict__ Wk, const float* __restrict__ bk,
                    const float* __restrict__ Wv, const float* __restrict__ bv)
{
    const int which = blockIdx.z;
    const float* X    = (which == 0) ? qin : (which == 1) ? kin : vin;
    const float* W    = (which == 0) ? Wq  : (which == 1) ? Wk  : Wv;
    const float* bias = (which == 0) ? bq  : (which == 1) ? bk  : bv;
    float* out        = (which == 0) ? g_q : (which == 1) ? g_k : g_v;

    __shared__ uint32_t As[128][KSTRIDE];
    __shared__ uint32_t Bs[128][KSTRIDE];

    const int m0 = blockIdx.y * 128;
    const int n0 = blockIdx.x * 128;
    const int tid = threadIdx.x;
    const int warp = tid >> 5, lane = tid & 31;
    const int wm = warp >> 2;
    const int wn = warp & 3;
    const int qr = lane >> 2;
    const int qc = lane & 3;

    float acc[4][4][4];
#pragma unroll
    for (int mi = 0; mi < 4; mi++)
#pragma unroll
        for (int ni = 0; ni < 4; ni++)
#pragma unroll
            for (int e = 0; e < 4; e++) acc[mi][ni][e] = 0.f;

    for (int k0 = 0; k0 < Hc; k0 += 32) {
#pragma unroll
        for (int l = 0; l < 4; l++) {
            int idx = tid + l * 256;
            int r = idx >> 3;
            int q = idx & 7;
            float4 a = *(const float4*)&X[(size_t)(m0 + r) * Hc + k0 + q * 4];
            As[r][q * 4 + 0] = f2tf32(a.x); As[r][q * 4 + 1] = f2tf32(a.y);
            As[r][q * 4 + 2] = f2tf32(a.z); As[r][q * 4 + 3] = f2tf32(a.w);
            float4 w = *(const float4*)&W[(size_t)(n0 + r) * Hc + k0 + q * 4];
            Bs[r][q * 4 + 0] = f2tf32(w.x); Bs[r][q * 4 + 1] = f2tf32(w.y);
            Bs[r][q * 4 + 2] = f2tf32(w.z); Bs[r][q * 4 + 3] = f2tf32(w.w);
        }
        __syncthreads();

#pragma unroll
        for (int ks = 0; ks < 4; ks++) {
            const int kk = ks * 8;
            uint32_t af[4][4];
#pragma unroll
            for (int mi = 0; mi < 4; mi++) {
                int row = wm * 64 + mi * 16 + qr;
                af[mi][0] = As[row    ][kk + qc];
                af[mi][1] = As[row + 8][kk + qc];
                af[mi][2] = As[row    ][kk + qc + 4];
                af[mi][3] = As[row + 8][kk + qc + 4];
            }
            uint32_t bf[4][2];
#pragma unroll
            for (int ni = 0; ni < 4; ni++) {
                int col = wn * 32 + ni * 8 + qr;
                bf[ni][0] = Bs[col][kk + qc];
                bf[ni][1] = Bs[col][kk + qc + 4];
            }
#pragma unroll
            for (int mi = 0; mi < 4; mi++)
#pragma unroll
                for (int ni = 0; ni < 4; ni++)
                    mma_tf32(acc[mi][ni], af[mi], bf[ni], acc[mi][ni]);
        }
        __syncthreads();
    }

#pragma unroll
    for (int mi = 0; mi < 4; mi++) {
#pragma unroll
        for (int half = 0; half < 2; half++) {
            int m = m0 + wm * 64 + mi * 16 + qr + half * 8;
            int bb = m >> 10;
            int s  = m & 1023;
#pragma unroll
            for (int ni = 0; ni < 4; ni++) {
                int n = n0 + wn * 32 + ni * 8 + qc * 2;
                int h = n >> 6, d = n & 63;
                float2 r;
                r.x = acc[mi][ni][half * 2 + 0] + bias[n];
                r.y = acc[mi][ni][half * 2 + 1] + bias[n + 1];
                *(float2*)&out[(((size_t)(bb * NHc + h)) << 16) + ((size_t)s << 6) + d] = r;
            }
        }
    }
}

// ---------------------------------------------------------------------------
// Kernel 2 (fused): scores + softmax + P@V, flash-style, mma.sync tf32.
// CTA = (bh, 64 query rows). 8 warps as 4 row-groups x 2 col-groups.
// Streams 8 j-chunks of 128. QK uses split-tf32 (hi/lo) for fp32-level
// accuracy on the scores output; PV uses single tf32 for P and V.
//
// Dyn smem word offsets (stride 68 for 64-wide, 132 for 128-wide):
//   QHI 0      (64x68)    QLO 4352
//   KHI 8704   (128x68)   KLO 17408
//   VS  26112  (128x68, tf32 bits of V)
//   PS  34816  (64x132, tf32 bits of P)
//   M 43264  L 43328  SC 43392  WMAX 43456(128)  WSUM 43584(128)
// total 43712 words = 174848 bytes.
// ---------------------------------------------------------------------------
#define AT_QHI 0
#define AT_QLO 4352
#define AT_KHI 8704
#define AT_KLO 17408
#define AT_VS  26112
#define AT_PS  34816
#define AT_M   43264
#define AT_L   43328
#define AT_SC  43392
#define AT_WMAX 43456
#define AT_WSUM 43584
#define AT_SMEM_BYTES 174848

__global__ __launch_bounds__(256)
void attn_fused_kernel(const int* __restrict__ mask,
                       float* __restrict__ scores,
                       float* __restrict__ ctx)
{
    extern __shared__ float smf[];
    uint32_t* smu = (uint32_t*)smf;

    const int bh = blockIdx.y;
    const int i0 = blockIdx.x * 64;
    const float* Q = g_q + ((size_t)bh << 16);
    const float* K = g_k + ((size_t)bh << 16);
    const float* V = g_v + ((size_t)bh << 16);

    const int tid = threadIdx.x;
    const int warp = tid >> 5, lane = tid & 31;
    const int qr = lane >> 2, qc = lane & 3;
    const int rg = warp >> 1, cg = warp & 1;
    const int rowLA = rg * 16 + qr, rowLB = rowLA + 8;

    // Stage Q tile (64x64) as hi/lo tf32
#pragma unroll
    for (int l = 0; l < 4; l++) {
        int idx = tid + l * 256;
        int r = idx >> 4, q4 = idx & 15;
        float4 a = *(const float4*)&Q[(size_t)(i0 + r) * HDc + q4 * 4];
        uint4 hi, lo;
        hi.x = f2tf32(a.x); lo.x = f2tf32(a.x - __uint_as_float(hi.x));
        hi.y = f2tf32(a.y); lo.y = f2tf32(a.y - __uint_as_float(hi.y));
        hi.z = f2tf32(a.z); lo.z = f2tf32(a.z - __uint_as_float(hi.z));
        hi.w = f2tf32(a.w); lo.w = f2tf32(a.w - __uint_as_float(hi.w));
        *(uint4*)&smu[AT_QHI + r * 68 + q4 * 4] = hi;
        *(uint4*)&smu[AT_QLO + r * 68 + q4 * 4] = lo;
    }
    if (tid < 64) { smf[AT_M + tid] = -1e30f; smf[AT_L + tid] = 0.f; }

    float pv[4][4];
#pragma unroll
    for (int ni = 0; ni < 4; ni++)
#pragma unroll
        for (int e = 0; e < 4; e++) pv[ni][e] = 0.f;

    for (int ch = 0; ch < 8; ch++) {
        const int j0 = ch * 128;
        __syncthreads();   // prev chunk's PV done; Q/stats ready on ch==0

        // Stage K (hi/lo) and V (tf32) chunk [128][64]
#pragma unroll
        for (int l = 0; l < 8; l++) {
            int idx = tid + l * 256;
            int r = idx >> 4, q4 = idx & 15;
            float4 k = *(const float4*)&K[(size_t)(j0 + r) * HDc + q4 * 4];
            uint4 hi, lo;
            hi.x = f2tf32(k.x); lo.x = f2tf32(k.x - __uint_as_float(hi.x));
            hi.y = f2tf32(k.y); lo.y = f2tf32(k.y - __uint_as_float(hi.y));
            hi.z = f2tf32(k.z); lo.z = f2tf32(k.z - __uint_as_float(hi.z));
            hi.w = f2tf32(k.w); lo.w = f2tf32(k.w - __uint_as_float(hi.w));
            *(uint4*)&smu[AT_KHI + r * 68 + q4 * 4] = hi;
            *(uint4*)&smu[AT_KLO + r * 68 + q4 * 4] = lo;
            float4 v = *(const float4*)&V[(size_t)(j0 + r) * HDc + q4 * 4];
            uint4 vb = { f2tf32(v.x), f2tf32(v.y), f2tf32(v.z), f2tf32(v.w) };
            *(uint4*)&smu[AT_VS + r * 68 + q4 * 4] = vb;
        }
        __syncthreads();

        // S = Q @ K^T over this chunk: warp tile 16 rows x 64 cols (8 n-frags)
        float sacc[8][4];
#pragma unroll
        for (int ni = 0; ni < 8; ni++)
#pragma unroll
            for (int e = 0; e < 4; e++) sacc[ni][e] = 0.f;

#pragma unroll
        for (int kk = 0; kk < 64; kk += 8) {
            uint32_t ahi[4], alo[4];
            {
                int ra = (rg * 16 + qr) * 68 + kk + qc;
                ahi[0] = smu[AT_QHI + ra];            ahi[2] = smu[AT_QHI + ra + 4];
                ahi[1] = smu[AT_QHI + ra + 8 * 68];   ahi[3] = smu[AT_QHI + ra + 8 * 68 + 4];
                alo[0] = smu[AT_QLO + ra];            alo[2] = smu[AT_QLO + ra + 4];
                alo[1] = smu[AT_QLO + ra + 8 * 68];   alo[3] = smu[AT_QLO + ra + 8 * 68 + 4];
            }
#pragma unroll
            for (int ni = 0; ni < 8; ni++) {
                int rb = (cg * 64 + ni * 8 + qr) * 68 + kk + qc;
                uint32_t bh_[2] = { smu[AT_KHI + rb], smu[AT_KHI + rb + 4] };
                uint32_t bl_[2] = { smu[AT_KLO + rb], smu[AT_KLO + rb + 4] };
                mma_tf32(sacc[ni], alo, bh_, sacc[ni]);
                mma_tf32(sacc[ni], ahi, bl_, sacc[ni]);
                mma_tf32(sacc[ni], ahi, bh_, sacc[ni]);
            }
        }

        // scale + mask + write scores; per-row max
        const int rowGA = i0 + rowLA, rowGB = i0 + rowLB;
        float rm0 = -3.4e38f, rm1 = -3.4e38f;
#pragma unroll
        for (int ni = 0; ni < 8; ni++) {
            int col = j0 + cg * 64 + ni * 8 + 2 * qc;
            size_t iA = (((size_t)bh << 10) + rowGA) * Sc + col;
            size_t iB = (((size_t)bh << 10) + rowGB) * Sc + col;
            int2 mA = *(const int2*)&mask[iA];
            int2 mB = *(const int2*)&mask[iB];
            float s0 = sacc[ni][0] * 0.125f + (mA.x ? -9999.0f : 0.0f);
            float s1 = sacc[ni][1] * 0.125f + (mA.y ? -9999.0f : 0.0f);
            float s2 = sacc[ni][2] * 0.125f + (mB.x ? -9999.0f : 0.0f);
            float s3 = sacc[ni][3] * 0.125f + (mB.y ? -9999.0f : 0.0f);
            float2 wA = { s0, s1 }, wB = { s2, s3 };
            *(float2*)&scores[iA] = wA;
            *(float2*)&scores[iB] = wB;
            sacc[ni][0] = s0; sacc[ni][1] = s1; sacc[ni][2] = s2; sacc[ni][3] = s3;
            rm0 = fmaxf(rm0, fmaxf(s0, s1));
            rm1 = fmaxf(rm1, fmaxf(s2, s3));
        }
        rm0 = fmaxf(rm0, __shfl_xor_sync(0xffffffffu, rm0, 1));
        rm0 = fmaxf(rm0, __shfl_xor_sync(0xffffffffu, rm0, 2));
        rm1 = fmaxf(rm1, __shfl_xor_sync(0xffffffffu, rm1, 1));
        rm1 = fmaxf(rm1, __shfl_xor_sync(0xffffffffu, rm1, 2));
        if (qc == 0) {
            smf[AT_WMAX + cg * 64 + rowLA] = rm0;
            smf[AT_WMAX + cg * 64 + rowLB] = rm1;
        }
        __syncthreads();

        if (tid < 64) {
            float mo = smf[AT_M + tid];
            float mn = fmaxf(mo, fmaxf(smf[AT_WMAX + tid], smf[AT_WMAX + 64 + tid]));
            smf[AT_SC + tid] = __expf(mo - mn);
            smf[AT_M + tid]  = mn;
        }
        __syncthreads();

        // P = exp(s - m_new) -> Ps (tf32); row sums; rescale PV acc
        const float mNA = smf[AT_M + rowLA], mNB = smf[AT_M + rowLB];
        const float scA = smf[AT_SC + rowLA], scB = smf[AT_SC + rowLB];
#pragma unroll
        for (int ni = 0; ni < 4; ni++) {
            pv[ni][0] *= scA; pv[ni][1] *= scA;
            pv[ni][2] *= scB; pv[ni][3] *= scB;
        }
        float rs0 = 0.f, rs1 = 0.f;
#pragma unroll
        for (int ni = 0; ni < 8; ni++) {
            float p0 = __expf(sacc[ni][0] - mNA);
            float p1 = __expf(sacc[ni][1] - mNA);
            float p2 = __expf(sacc[ni][2] - mNB);
            float p3 = __expf(sacc[ni][3] - mNB);
            rs0 += p0 + p1; rs1 += p2 + p3;
            int c = cg * 64 + ni * 8 + 2 * qc;
            smu[AT_PS + rowLA * 132 + c]     = f2tf32(p0);
            smu[AT_PS + rowLA * 132 + c + 1] = f2tf32(p1);
            smu[AT_PS + rowLB * 132 + c]     = f2tf32(p2);
            smu[AT_PS + rowLB * 132 + c + 1] = f2tf32(p3);
        }
        rs0 += __shfl_xor_sync(0xffffffffu, rs0, 1);
        rs0 += __shfl_xor_sync(0xffffffffu, rs0, 2);
        rs1 += __shfl_xor_sync(0xffffffffu, rs1, 1);
        rs1 += __shfl_xor_sync(0xffffffffu, rs1, 2);
        if (qc == 0) {
            smf[AT_WSUM + cg * 64 + rowLA] = rs0;
            smf[AT_WSUM + cg * 64 + rowLB] = rs1;
        }
        __syncthreads();

        if (tid < 64)
            smf[AT_L + tid] = smf[AT_L + tid] * smf[AT_SC + tid]
                              + smf[AT_WSUM + tid] + smf[AT_WSUM + 64 + tid];

        // PV: ctx_acc += P(64x128) @ V(128x64); warp tile 16 rows x 32 d
#pragma unroll
        for (int kk = 0; kk < 128; kk += 8) {
            uint32_t a[4];
            a[0] = smu[AT_PS + rowLA * 132 + kk + qc];
            a[1] = smu[AT_PS + rowLB * 132 + kk + qc];
            a[2] = smu[AT_PS + rowLA * 132 + kk + qc + 4];
            a[3] = smu[AT_PS + rowLB * 132 + kk + qc + 4];
#pragma unroll
            for (int ni = 0; ni < 4; ni++) {
                int nb = cg * 32 + ni * 8 + qr;
                uint32_t b[2] = { smu[AT_VS + (kk + qc) * 68 + nb],
                                  smu[AT_VS + (kk + qc + 4) * 68 + nb] };
                mma_tf32(pv[ni], a, b, pv[ni]);
            }
        }
    }

    __syncthreads();   // L final

    // Epilogue: ctx[b][s][h*64+d] = pv / l
    const float invA = 1.0f / smf[AT_L + rowLA];
    const float invB = 1.0f / smf[AT_L + rowLB];
    const int b_ = bh >> 4, h_ = bh & 15;
    const size_t oA = (((size_t)b_ << 10) + (i0 + rowLA)) * Hc + h_ * HDc;
    const size_t oB = (((size_t)b_ << 10) + (i0 + rowLB)) * Hc + h_ * HDc;
#pragma unroll
    for (int ni = 0; ni < 4; ni++) {
        int d = cg * 32 + ni * 8 + 2 * qc;
        float2 rA = { pv[ni][0] * invA, pv[ni][1] * invA };
        float2 rB = { pv[ni][2] * invB, pv[ni][3] * invB };
        *(float2*)&ctx[oA + d] = rA;
        *(float2*)&ctx[oB + d] = rB;
    }
}

// ---------------------------------------------------------------------------
extern "C" void kernel_launch(void* const* d_in, const int* in_sizes, int n_in,
                              void* d_out, int out_size)
{
    const float* qin = (const float*)d_in[0];
    const float* kin = (const float*)d_in[1];
    const float* vin = (const float*)d_in[2];
    const int* mask  = (const int*)d_in[3];      // bool widened to int32
    const float* Wq = (const float*)d_in[4];
    const float* bq = (const float*)d_in[5];
    const float* Wk = (const float*)d_in[6];
    const float* bk = (const float*)d_in[7];
    const float* Wv = (const float*)d_in[8];
    const float* bv = (const float*)d_in[9];

    float* ctx = (float*)d_out;
    float* scores;
    if (out_size >= CTX_ELEMS + SCORES_ELEMS) {
        scores = (float*)d_out + CTX_ELEMS;          // tuple output (ctx, scores)
    } else {
        cudaGetSymbolAddress((void**)&scores, g_scores_scratch);
    }

    // 1) QKV projections via legacy tensor cores (tf32 mma.sync)
    {
        dim3 grid(Hc / 128, Mrows / 128, 3);
        qkv_mma_kernel<<<grid, 256>>>(qin, kin, vin, Wq, bq, Wk, bk, Wv, bv);
    }
    // 2) fused scores + softmax + P@V
    {
        cudaFuncSetAttribute(attn_fused_kernel,
                             cudaFuncAttributeMaxDynamicSharedMemorySize, AT_SMEM_BYTES);
        dim3 grid(Sc / 64, BHc);
        attn_fused_kernel<<<grid, 256, AT_SMEM_BYTES>>>(mask, scores, ctx);
    }
}

// round 16
// speedup vs baseline: 2.1216x; 1.1210x over previous
#include <cuda_runtime.h>
#include <cstdint>

// Problem constants
#define Bc 4
#define Sc 1024
#define Hc 1024
#define NHc 16
#define HDc 64
#define BHc (Bc * NHc)                 // 64
#define Mrows (Bc * Sc)                // 4096
#define CTX_ELEMS (Bc * Sc * Hc)       // 4194304
#define SCORES_ELEMS (BHc * Sc * Sc)   // 67108864

// Scratch (device globals — no runtime allocation allowed)
__device__ float g_q[BHc * Sc * HDc];   // [bh][s][d]
__device__ float g_k[BHc * Sc * HDc];
__device__ float g_v[BHc * Sc * HDc];
__device__ float g_scores_scratch[SCORES_ELEMS]; // fallback if scores not in d_out

// ---------------------------------------------------------------------------
// tf32 helpers (legacy tensor-core path: works on compute_103 baseline)
// ---------------------------------------------------------------------------
__device__ __forceinline__ uint32_t f2tf32(float f) {
    uint32_t r;
    asm("cvt.rna.tf32.f32 %0, %1;" : "=r"(r) : "f"(f));
    return r;
}

__device__ __forceinline__ void mma_tf32(float (&d)[4],
                                         const uint32_t (&a)[4],
                                         const uint32_t (&b)[2],
                                         const float (&c)[4]) {
    asm volatile(
        "mma.sync.aligned.m16n8k8.row.col.f32.tf32.tf32.f32 "
        "{%0,%1,%2,%3}, {%4,%5,%6,%7}, {%8,%9}, {%10,%11,%12,%13};"
        : "=f"(d[0]), "=f"(d[1]), "=f"(d[2]), "=f"(d[3])
        : "r"(a[0]), "r"(a[1]), "r"(a[2]), "r"(a[3]),
          "r"(b[0]), "r"(b[1]),
          "f"(c[0]), "f"(c[1]), "f"(c[2]), "f"(c[3]));
}

// ---------------------------------------------------------------------------
// Kernel 1: QKV projection via mma.sync tf32.  (unchanged - passing)
// ---------------------------------------------------------------------------
#define KSTRIDE 36

__global__ __launch_bounds__(256, 2)
void qkv_mma_kernel(const float* __restrict__ qin, const float* __restrict__ kin,
                    const float* __restrict__ vin,
                    const float* __restrict__ Wq, const float* __restrict__ bq,
                    const float* __restrict__ Wk, const float* __restrict__ bk,
                    const float* __restrict__ Wv, const float* __restrict__ bv)
{
    const int which = blockIdx.z;
    const float* X    = (which == 0) ? qin : (which == 1) ? kin : vin;
    const float* W    = (which == 0) ? Wq  : (which == 1) ? Wk  : Wv;
    const float* bias = (which == 0) ? bq  : (which == 1) ? bk  : bv;
    float* out        = (which == 0) ? g_q : (which == 1) ? g_k : g_v;

    __shared__ uint32_t As[128][KSTRIDE];
    __shared__ uint32_t Bs[128][KSTRIDE];

    const int m0 = blockIdx.y * 128;
    const int n0 = blockIdx.x * 128;
    const int tid = threadIdx.x;
    const int warp = tid >> 5, lane = tid & 31;
    const int wm = warp >> 2;
    const int wn = warp & 3;
    const int qr = lane >> 2;
    const int qc = lane & 3;

    float acc[4][4][4];
#pragma unroll
    for (int mi = 0; mi < 4; mi++)
#pragma unroll
        for (int ni = 0; ni < 4; ni++)
#pragma unroll
            for (int e = 0; e < 4; e++) acc[mi][ni][e] = 0.f;

    for (int k0 = 0; k0 < Hc; k0 += 32) {
#pragma unroll
        for (int l = 0; l < 4; l++) {
            int idx = tid + l * 256;
            int r = idx >> 3;
            int q = idx & 7;
            float4 a = *(const float4*)&X[(size_t)(m0 + r) * Hc + k0 + q * 4];
            As[r][q * 4 + 0] = f2tf32(a.x); As[r][q * 4 + 1] = f2tf32(a.y);
            As[r][q * 4 + 2] = f2tf32(a.z); As[r][q * 4 + 3] = f2tf32(a.w);
            float4 w = *(const float4*)&W[(size_t)(n0 + r) * Hc + k0 + q * 4];
            Bs[r][q * 4 + 0] = f2tf32(w.x); Bs[r][q * 4 + 1] = f2tf32(w.y);
            Bs[r][q * 4 + 2] = f2tf32(w.z); Bs[r][q * 4 + 3] = f2tf32(w.w);
        }
        __syncthreads();

#pragma unroll
        for (int ks = 0; ks < 4; ks++) {
            const int kk = ks * 8;
            uint32_t af[4][4];
#pragma unroll
            for (int mi = 0; mi < 4; mi++) {
                int row = wm * 64 + mi * 16 + qr;
                af[mi][0] = As[row    ][kk + qc];
                af[mi][1] = As[row + 8][kk + qc];
                af[mi][2] = As[row    ][kk + qc + 4];
                af[mi][3] = As[row + 8][kk + qc + 4];
            }
            uint32_t bf[4][2];
#pragma unroll
            for (int ni = 0; ni < 4; ni++) {
                int col = wn * 32 + ni * 8 + qr;
                bf[ni][0] = Bs[col][kk + qc];
                bf[ni][1] = Bs[col][kk + qc + 4];
            }
#pragma unroll
            for (int mi = 0; mi < 4; mi++)
#pragma unroll
                for (int ni = 0; ni < 4; ni++)
                    mma_tf32(acc[mi][ni], af[mi], bf[ni], acc[mi][ni]);
        }
        __syncthreads();
    }

#pragma unroll
    for (int mi = 0; mi < 4; mi++) {
#pragma unroll
        for (int half = 0; half < 2; half++) {
            int m = m0 + wm * 64 + mi * 16 + qr + half * 8;
            int bb = m >> 10;
            int s  = m & 1023;
#pragma unroll
            for (int ni = 0; ni < 4; ni++) {
                int n = n0 + wn * 32 + ni * 8 + qc * 2;
                int h = n >> 6, d = n & 63;
                float2 r;
                r.x = acc[mi][ni][half * 2 + 0] + bias[n];
                r.y = acc[mi][ni][half * 2 + 1] + bias[n + 1];
                *(float2*)&out[(((size_t)(bb * NHc + h)) << 16) + ((size_t)s << 6) + d] = r;
            }
        }
    }
}

// ---------------------------------------------------------------------------
// Kernel 2 (fused): scores + softmax + P@V, flash-style, mma.sync tf32.
// CTA = (bh, 64 query rows). 8 warps as 4 row-groups x 2 col-groups.
// j-chunk = 64 (16 iterations) -> smem ~104KB -> 2 CTA/SM (was 1).
// QK split-tf32 (hi/lo both sides); PV single tf32.
//
// Dyn smem word offsets (stride 68):
//   QHI 0 (64x68)  QLO 4352  KHI 8704  KLO 13056  VS 17408  PS 21760
//   M 26112(64)  L 26176(64)  SC 26240(64)  WMAX 26304(128)  WSUM 26432(128)
// total 26560 words = 106240 bytes
// ---------------------------------------------------------------------------
#define AT_QHI 0
#define AT_QLO 4352
#define AT_KHI 8704
#define AT_KLO 13056
#define AT_VS  17408
#define AT_PS  21760
#define AT_M   26112
#define AT_L   26176
#define AT_SC  26240
#define AT_WMAX 26304
#define AT_WSUM 26432
#define AT_SMEM_BYTES 106240

__global__ __launch_bounds__(256, 2)
void attn_fused_kernel(const int* __restrict__ mask,
                       float* __restrict__ scores,
                       float* __restrict__ ctx)
{
    extern __shared__ float smf[];
    uint32_t* smu = (uint32_t*)smf;

    const int bh = blockIdx.y;
    const int i0 = blockIdx.x * 64;
    const float* Q = g_q + ((size_t)bh << 16);
    const float* K = g_k + ((size_t)bh << 16);
    const float* V = g_v + ((size_t)bh << 16);

    const int tid = threadIdx.x;
    const int warp = tid >> 5, lane = tid & 31;
    const int qr = lane >> 2, qc = lane & 3;
    const int rg = warp >> 1, cg = warp & 1;
    const int rowLA = rg * 16 + qr, rowLB = rowLA + 8;

    // Stage Q tile (64x64) as hi/lo tf32
#pragma unroll
    for (int l = 0; l < 4; l++) {
        int idx = tid + l * 256;
        int r = idx >> 4, q4 = idx & 15;
        float4 a = *(const float4*)&Q[(size_t)(i0 + r) * HDc + q4 * 4];
        uint4 hi, lo;
        hi.x = f2tf32(a.x); lo.x = f2tf32(a.x - __uint_as_float(hi.x));
        hi.y = f2tf32(a.y); lo.y = f2tf32(a.y - __uint_as_float(hi.y));
        hi.z = f2tf32(a.z); lo.z = f2tf32(a.z - __uint_as_float(hi.z));
        hi.w = f2tf32(a.w); lo.w = f2tf32(a.w - __uint_as_float(hi.w));
        *(uint4*)&smu[AT_QHI + r * 68 + q4 * 4] = hi;
        *(uint4*)&smu[AT_QLO + r * 68 + q4 * 4] = lo;
    }
    if (tid < 64) { smf[AT_M + tid] = -1e30f; smf[AT_L + tid] = 0.f; }

    float pv[4][4];
#pragma unroll
    for (int ni = 0; ni < 4; ni++)
#pragma unroll
        for (int e = 0; e < 4; e++) pv[ni][e] = 0.f;

    for (int ch = 0; ch < 16; ch++) {
        const int j0 = ch * 64;
        __syncthreads();   // prev chunk's PV done reading KS/VS/PS

        // Stage K (hi/lo) and V (tf32) chunk [64][64]
#pragma unroll
        for (int l = 0; l < 4; l++) {
            int idx = tid + l * 256;
            int r = idx >> 4, q4 = idx & 15;
            float4 k = *(const float4*)&K[(size_t)(j0 + r) * HDc + q4 * 4];
            uint4 hi, lo;
            hi.x = f2tf32(k.x); lo.x = f2tf32(k.x - __uint_as_float(hi.x));
            hi.y = f2tf32(k.y); lo.y = f2tf32(k.y - __uint_as_float(hi.y));
            hi.z = f2tf32(k.z); lo.z = f2tf32(k.z - __uint_as_float(hi.z));
            hi.w = f2tf32(k.w); lo.w = f2tf32(k.w - __uint_as_float(hi.w));
            *(uint4*)&smu[AT_KHI + r * 68 + q4 * 4] = hi;
            *(uint4*)&smu[AT_KLO + r * 68 + q4 * 4] = lo;
            float4 v = *(const float4*)&V[(size_t)(j0 + r) * HDc + q4 * 4];
            uint4 vb = { f2tf32(v.x), f2tf32(v.y), f2tf32(v.z), f2tf32(v.w) };
            *(uint4*)&smu[AT_VS + r * 68 + q4 * 4] = vb;
        }
        __syncthreads();

        // S = Q @ K^T over this chunk: warp tile 16 rows x 32 cols (4 n-frags)
        float sacc[4][4];
#pragma unroll
        for (int ni = 0; ni < 4; ni++)
#pragma unroll
            for (int e = 0; e < 4; e++) sacc[ni][e] = 0.f;

#pragma unroll
        for (int kk = 0; kk < 64; kk += 8) {
            uint32_t ahi[4], alo[4];
            {
                int ra = (rg * 16 + qr) * 68 + kk + qc;
                ahi[0] = smu[AT_QHI + ra];            ahi[2] = smu[AT_QHI + ra + 4];
                ahi[1] = smu[AT_QHI + ra + 8 * 68];   ahi[3] = smu[AT_QHI + ra + 8 * 68 + 4];
                alo[0] = smu[AT_QLO + ra];            alo[2] = smu[AT_QLO + ra + 4];
                alo[1] = smu[AT_QLO + ra + 8 * 68];   alo[3] = smu[AT_QLO + ra + 8 * 68 + 4];
            }
#pragma unroll
            for (int ni = 0; ni < 4; ni++) {
                int rb = (cg * 32 + ni * 8 + qr) * 68 + kk + qc;
                uint32_t bh_[2] = { smu[AT_KHI + rb], smu[AT_KHI + rb + 4] };
                uint32_t bl_[2] = { smu[AT_KLO + rb], smu[AT_KLO + rb + 4] };
                mma_tf32(sacc[ni], alo, bh_, sacc[ni]);
                mma_tf32(sacc[ni], ahi, bl_, sacc[ni]);
                mma_tf32(sacc[ni], ahi, bh_, sacc[ni]);
            }
        }

        // scale + mask + write scores; per-row max
        const int rowGA = i0 + rowLA, rowGB = i0 + rowLB;
        float rm0 = -3.4e38f, rm1 = -3.4e38f;
#pragma unroll
        for (int ni = 0; ni < 4; ni++) {
            int col = j0 + cg * 32 + ni * 8 + 2 * qc;
            size_t iA = (((size_t)bh << 10) + rowGA) * Sc + col;
            size_t iB = (((size_t)bh << 10) + rowGB) * Sc + col;
            int2 mA = *(const int2*)&mask[iA];
            int2 mB = *(const int2*)&mask[iB];
            float s0 = sacc[ni][0] * 0.125f + (mA.x ? -9999.0f : 0.0f);
            float s1 = sacc[ni][1] * 0.125f + (mA.y ? -9999.0f : 0.0f);
            float s2 = sacc[ni][2] * 0.125f + (mB.x ? -9999.0f : 0.0f);
            float s3 = sacc[ni][3] * 0.125f + (mB.y ? -9999.0f : 0.0f);
            float2 wA = { s0, s1 }, wB = { s2, s3 };
            *(float2*)&scores[iA] = wA;
            *(float2*)&scores[iB] = wB;
            sacc[ni][0] = s0; sacc[ni][1] = s1; sacc[ni][2] = s2; sacc[ni][3] = s3;
            rm0 = fmaxf(rm0, fmaxf(s0, s1));
            rm1 = fmaxf(rm1, fmaxf(s2, s3));
        }
        rm0 = fmaxf(rm0, __shfl_xor_sync(0xffffffffu, rm0, 1));
        rm0 = fmaxf(rm0, __shfl_xor_sync(0xffffffffu, rm0, 2));
        rm1 = fmaxf(rm1, __shfl_xor_sync(0xffffffffu, rm1, 1));
        rm1 = fmaxf(rm1, __shfl_xor_sync(0xffffffffu, rm1, 2));
        if (qc == 0) {
            smf[AT_WMAX + cg * 64 + rowLA] = rm0;
            smf[AT_WMAX + cg * 64 + rowLB] = rm1;
        }
        __syncthreads();

        if (tid < 64) {
            float mo = smf[AT_M + tid];
            float mn = fmaxf(mo, fmaxf(smf[AT_WMAX + tid], smf[AT_WMAX + 64 + tid]));
            smf[AT_SC + tid] = __expf(mo - mn);
            smf[AT_M + tid]  = mn;
        }
        __syncthreads();

        // P = exp(s - m_new) -> Ps (tf32); row sums; rescale PV acc
        const float mNA = smf[AT_M + rowLA], mNB = smf[AT_M + rowLB];
        const float scA = smf[AT_SC + rowLA], scB = smf[AT_SC + rowLB];
#pragma unroll
        for (int ni = 0; ni < 4; ni++) {
            pv[ni][0] *= scA; pv[ni][1] *= scA;
            pv[ni][2] *= scB; pv[ni][3] *= scB;
        }
        float rs0 = 0.f, rs1 = 0.f;
#pragma unroll
        for (int ni = 0; ni < 4; ni++) {
            float p0 = __expf(sacc[ni][0] - mNA);
            float p1 = __expf(sacc[ni][1] - mNA);
            float p2 = __expf(sacc[ni][2] - mNB);
            float p3 = __expf(sacc[ni][3] - mNB);
            rs0 += p0 + p1; rs1 += p2 + p3;
            int c = cg * 32 + ni * 8 + 2 * qc;
            smu[AT_PS + rowLA * 68 + c]     = f2tf32(p0);
            smu[AT_PS + rowLA * 68 + c + 1] = f2tf32(p1);
            smu[AT_PS + rowLB * 68 + c]     = f2tf32(p2);
            smu[AT_PS + rowLB * 68 + c + 1] = f2tf32(p3);
        }
        rs0 += __shfl_xor_sync(0xffffffffu, rs0, 1);
        rs0 += __shfl_xor_sync(0xffffffffu, rs0, 2);
        rs1 += __shfl_xor_sync(0xffffffffu, rs1, 1);
        rs1 += __shfl_xor_sync(0xffffffffu, rs1, 2);
        if (qc == 0) {
            smf[AT_WSUM + cg * 64 + rowLA] = rs0;
            smf[AT_WSUM + cg * 64 + rowLB] = rs1;
        }
        __syncthreads();

        if (tid < 64)
            smf[AT_L + tid] = smf[AT_L + tid] * smf[AT_SC + tid]
                              + smf[AT_WSUM + tid] + smf[AT_WSUM + 64 + tid];

        // PV: ctx_acc += P(64x64) @ V(64x64); warp tile 16 rows x 32 d
#pragma unroll
        for (int kk = 0; kk < 64; kk += 8) {
            uint32_t a[4];
            a[0] = smu[AT_PS + rowLA * 68 + kk + qc];
            a[1] = smu[AT_PS + rowLB * 68 + kk + qc];
            a[2] = smu[AT_PS + rowLA * 68 + kk + qc + 4];
            a[3] = smu[AT_PS + rowLB * 68 + kk + qc + 4];
#pragma unroll
            for (int ni = 0; ni < 4; ni++) {
                int nb = cg * 32 + ni * 8 + qr;
                uint32_t b[2] = { smu[AT_VS + (kk + qc) * 68 + nb],
                                  smu[AT_VS + (kk + qc + 4) * 68 + nb] };
                mma_tf32(pv[ni], a, b, pv[ni]);
            }
        }
    }

    __syncthreads();   // L final

    // Epilogue: ctx[b][s][h*64+d] = pv / l
    const float invA = 1.0f / smf[AT_L + rowLA];
    const float invB = 1.0f / smf[AT_L + rowLB];
    const int b_ = bh >> 4, h_ = bh & 15;
    const size_t oA = (((size_t)b_ << 10) + (i0 + rowLA)) * Hc + h_ * HDc;
    const size_t oB = (((size_t)b_ << 10) + (i0 + rowLB)) * Hc + h_ * HDc;
#pragma unroll
    for (int ni = 0; ni < 4; ni++) {
        int d = cg * 32 + ni * 8 + 2 * qc;
        float2 rA = { pv[ni][0] * invA, pv[ni][1] * invA };
        float2 rB = { pv[ni][2] * invB, pv[ni][3] * invB };
        *(float2*)&ctx[oA + d] = rA;
        *(float2*)&ctx[oB + d] = rB;
    }
}

// ---------------------------------------------------------------------------
extern "C" void kernel_launch(void* const* d_in, const int* in_sizes, int n_in,
                              void* d_out, int out_size)
{
    const float* qin = (const float*)d_in[0];
    const float* kin = (const float*)d_in[1];
    const float* vin = (const float*)d_in[2];
    const int* mask  = (const int*)d_in[3];      // bool widened to int32
    const float* Wq = (const float*)d_in[4];
    const float* bq = (const float*)d_in[5];
    const float* Wk = (const float*)d_in[6];
    const float* bk = (const float*)d_in[7];
    const float* Wv = (const float*)d_in[8];
    const float* bv = (const float*)d_in[9];

    float* ctx = (float*)d_out;
    float* scores;
    if (out_size >= CTX_ELEMS + SCORES_ELEMS) {
        scores = (float*)d_out + CTX_ELEMS;          // tuple output (ctx, scores)
    } else {
        cudaGetSymbolAddress((void**)&scores, g_scores_scratch);
    }

    // 1) QKV projections via legacy tensor cores (tf32 mma.sync)
    {
        dim3 grid(Hc / 128, Mrows / 128, 3);
        qkv_mma_kernel<<<grid, 256>>>(qin, kin, vin, Wq, bq, Wk, bk, Wv, bv);
    }
    // 2) fused scores + softmax + P@V
    {
        cudaFuncSetAttribute(attn_fused_kernel,
                             cudaFuncAttributeMaxDynamicSharedMemorySize, AT_SMEM_BYTES);
        dim3 grid(Sc / 64, BHc);
        attn_fused_kernel<<<grid, 256, AT_SMEM_BYTES>>>(mask, scores, ctx);
    }
}